// round 5
// baseline (speedup 1.0000x reference)
#include <cuda_runtime.h>

#define NBINS 8192
#define N_LEV 1024
#define XMIN_F (-4.25f)
#define XMAX_F (4.25f)

__device__ float g_grid[N_LEV];
__device__ float g_lut[N_LEV];
__device__ uint4 g_bins4[NBINS];

// ---------------------------------------------------------------------------
// Exact reference nearest-index (searchsorted 'left' + abs-distance compare).
// ---------------------------------------------------------------------------
__device__ __forceinline__ int nidx_exact_s(float x, const float* __restrict__ grid)
{
    int l = 0, r = N_LEV;                 // first i with grid[i] >= x
    while (l < r) {
        int m = (l + r) >> 1;
        if (grid[m] < x) l = m + 1; else r = m;
    }
    int idx = l < 1 ? 1 : (l > N_LEV - 1 ? N_LEV - 1 : l);
    float left  = grid[idx - 1];
    float right = grid[idx];
    return (fabsf(x - left) < fabsf(x - right)) ? idx - 1 : idx;
}

// ---------------------------------------------------------------------------
// Fused prep (1 block, 1024 threads).
// Per bin j, record = {X*, outL, outR, flag}:
//   - 0 or 1 decision boundary in bin: out = (x <= X*) ? outL : outR.
//     X* = exact largest float for which the reference picks the left level,
//     found by fp bisection on pred(x) = |x-l| < |x-r|, which is monotone
//     (true->false) in x. Bit-exact threshold semantics.
//   - >=2 boundaries in bin (rare): flag=1, {y,z}={lo,hi}, cold exact scan.
// Widened bin edges (+-0.25*W) absorb quantizer fp slop between prep & main.
// ---------------------------------------------------------------------------
__global__ void prep_all(const float* __restrict__ h,
                         const float* __restrict__ d,
                         const float* __restrict__ T,
                         const float* __restrict__ b)
{
    __shared__ float s_grid[N_LEV];
    __shared__ float s_lut[N_LEV];

    int i = threadIdx.x;
    float hv[9];
#pragma unroll
    for (int t = 0; t < 9; ++t) hv[t] = h[i * 9 + t];   // independent loads

    float v = hv[0];
    s_grid[i] = v;
    g_grid[i] = v;
    float out = 0.0f;
#pragma unroll
    for (int t = 1; t <= 8; ++t) {
        if (v - T[t] >= 0.0f) out += d[t];
        if (t != 8) v = hv[t + 1];
    }
    out -= b[0];
    s_lut[i] = out;
    g_lut[i] = out;
    __syncthreads();

    const float W = (XMAX_F - XMIN_F) / (float)NBINS;
#pragma unroll
    for (int k = 0; k < NBINS / N_LEV; ++k) {
        int j = i + k * N_LEV;
        float eL = XMIN_F + (float)j       * W - 0.25f * W;
        float eR = XMIN_F + (float)(j + 1) * W + 0.25f * W;
        int lo = nidx_exact_s(eL, s_grid);
        int hi = nidx_exact_s(eR, s_grid);
        uint4 rec;
        if (lo == hi) {
            rec.x = 0x7F800000u;                         // +inf: always left
            rec.y = rec.z = __float_as_uint(s_lut[lo]);
            rec.w = 0u;
        } else if (hi == lo + 1) {
            float l = s_grid[lo], r = s_grid[hi];
            rec.y = __float_as_uint(s_lut[lo]);
            rec.z = __float_as_uint(s_lut[hi]);
            rec.w = 0u;
            if (!(l < r)) {
                rec.x = 0xFF800000u;                     // -inf: always right
            } else {
                // bisect to adjacent floats: a = largest x with pred true
                float a = l, bb = r;
                for (int it = 0; it < 64; ++it) {
                    float m = 0.5f * (a + bb);
                    if (!(m > a && m < bb)) break;       // adjacent -> done
                    if (fabsf(m - l) < fabsf(m - r)) a = m; else bb = m;
                }
                rec.x = __float_as_uint(a);
            }
        } else {
            rec.x = 0u;
            rec.y = (unsigned)lo;
            rec.z = (unsigned)hi;
            rec.w = 1u;                                  // cold path
        }
        g_bins4[j] = rec;
    }
}

// ---------------------------------------------------------------------------
// Main kernel: branchless hot path (1 LDS.128 + FSETP + 2xSEL per element).
// ---------------------------------------------------------------------------
__device__ __forceinline__ float eval_one(float x,
                                          const uint4* __restrict__ s_bins4,
                                          const float* __restrict__ s_grid,
                                          const float* __restrict__ s_lut)
{
    const float scale = (float)NBINS / (XMAX_F - XMIN_F);
    float t = (x - XMIN_F) * scale;
    int j = (int)t;
    j = j < 0 ? 0 : (j > NBINS - 1 ? NBINS - 1 : j);
    uint4 rec = s_bins4[j];
    float res = (x <= __uint_as_float(rec.x)) ? __uint_as_float(rec.y)
                                              : __uint_as_float(rec.z);
    if (rec.w) {                                // ~0.4% of elements
        int nidx = (int)rec.y;
        int hi   = (int)rec.z;
        float gl = s_grid[nidx];
        while (nidx < hi) {
            float gr = s_grid[nidx + 1];
            if (fabsf(x - gl) < fabsf(x - gr)) break;   // exact ref tie-break
            ++nidx; gl = gr;
        }
        res = s_lut[nidx];
    }
    return res;
}

#define SMEM_BYTES (NBINS * 16 + 2 * N_LEV * 4)

__global__ void __launch_bounds__(1024, 1)
ps_act_main(const float4* __restrict__ xin, float4* __restrict__ oout,
            int n4, const float* __restrict__ xs, float* __restrict__ os, int n)
{
    extern __shared__ unsigned char smem_raw[];
    uint4* const s_bins4 = (uint4*)smem_raw;
    float* const s_grid  = (float*)(s_bins4 + NBINS);
    float* const s_lut   = s_grid + N_LEV;

    for (int i = threadIdx.x; i < NBINS; i += blockDim.x) s_bins4[i] = g_bins4[i];
    for (int i = threadIdx.x; i < N_LEV; i += blockDim.x) {
        s_grid[i] = g_grid[i];
        s_lut[i]  = g_lut[i];
    }
    __syncthreads();

    const int tid = blockIdx.x * blockDim.x + threadIdx.x;
    const int nt  = gridDim.x * blockDim.x;

    // Coalesced unroll-2 at offsets (i, i+nt): every LDG.128/STG.128 is a
    // fully-coalesced 512B warp transaction; two loads in flight per thread.
    int i = tid;
    for (; i + nt < n4; i += 2 * nt) {
        float4 a = xin[i];
        float4 c = xin[i + nt];
        float4 ra, rc;
        ra.x = eval_one(a.x, s_bins4, s_grid, s_lut);
        ra.y = eval_one(a.y, s_bins4, s_grid, s_lut);
        ra.z = eval_one(a.z, s_bins4, s_grid, s_lut);
        ra.w = eval_one(a.w, s_bins4, s_grid, s_lut);
        rc.x = eval_one(c.x, s_bins4, s_grid, s_lut);
        rc.y = eval_one(c.y, s_bins4, s_grid, s_lut);
        rc.z = eval_one(c.z, s_bins4, s_grid, s_lut);
        rc.w = eval_one(c.w, s_bins4, s_grid, s_lut);
        oout[i]      = ra;
        oout[i + nt] = rc;
    }
    if (i < n4) {
        float4 a = xin[i];
        float4 ra;
        ra.x = eval_one(a.x, s_bins4, s_grid, s_lut);
        ra.y = eval_one(a.y, s_bins4, s_grid, s_lut);
        ra.z = eval_one(a.z, s_bins4, s_grid, s_lut);
        ra.w = eval_one(a.w, s_bins4, s_grid, s_lut);
        oout[i] = ra;
    }

    // scalar tail (empty for this shape)
    for (int k = n4 * 4 + tid; k < n; k += nt)
        os[k] = eval_one(xs[k], s_bins4, s_grid, s_lut);
}

// ---------------------------------------------------------------------------
extern "C" void kernel_launch(void* const* d_in, const int* in_sizes, int n_in,
                              void* d_out, int out_size)
{
    const float* x = (const float*)d_in[0];
    const float* h = (const float*)d_in[1];
    const float* d = (const float*)d_in[2];
    const float* T = (const float*)d_in[3];
    const float* b = (const float*)d_in[4];
    float* out = (float*)d_out;
    int n  = in_sizes[0];
    int n4 = n >> 2;

    cudaFuncSetAttribute(ps_act_main,
                         cudaFuncAttributeMaxDynamicSharedMemorySize, SMEM_BYTES);

    prep_all<<<1, 1024>>>(h, d, T, b);

    ps_act_main<<<152, 1024, SMEM_BYTES>>>((const float4*)x, (float4*)out,
                                           n4, x, out, n);
}